// round 1
// baseline (speedup 1.0000x reference)
#include <cuda_runtime.h>
#include <math.h>

// Problem constants
#define N_      16
#define C_      128
#define S_      16384
#define K_      64

#define SP      64                 // positions per sub-tile
#define CHUNKS  32                 // S-chunks per n
#define SCHUNK  (S_ / CHUNKS)      // 512 positions per block
#define NSUB    (SCHUNK / SP)      // 8 sub-tiles per block
#define NBLOCKS (N_ * CHUNKS)      // 512 blocks
#define THREADS 256

// Deterministic scratch (no allocations allowed): per-block partials.
__device__ float g_part[(size_t)NBLOCKS * K_ * C_];   // 16.78 MB
__device__ float g_apart[NBLOCKS * K_];               // 131 KB

// Dynamic smem layout (floats):
//   xs   [C_][SP+1]   = 128*65  = 8320
//   Ws   [K_][C_]     = 64*128  = 8192
//   lg   [K_][SP+1]   = 64*65   = 4160
//   part [4][SP]      = 256
//   inn  [SP]         = 64
//   bsh  [K_]         = 64
#define SM_XS    0
#define SM_WS    (SM_XS + C_ * (SP + 1))
#define SM_LG    (SM_WS + K_ * C_)
#define SM_PART  (SM_LG + K_ * (SP + 1))
#define SM_INN   (SM_PART + 4 * SP)
#define SM_BSH   (SM_INN + SP)
#define SM_FLTS  (SM_BSH + K_)
#define MAIN_SMEM_BYTES (SM_FLTS * sizeof(float))

__global__ __launch_bounds__(THREADS, 2)
void netvlad_main_kernel(const float* __restrict__ x,
                         const float* __restrict__ fc_w,
                         const float* __restrict__ fc_b)
{
    extern __shared__ float sm[];
    float* xs_f  = sm + SM_XS;    // [C_][SP+1]
    float* Ws_f  = sm + SM_WS;    // [K_][C_]
    float* lg_f  = sm + SM_LG;    // [K_][SP+1]
    float* partb = sm + SM_PART;  // [4][SP]
    float* inn   = sm + SM_INN;   // [SP]
    float* bsh   = sm + SM_BSH;   // [K_]

    const int t     = threadIdx.x;
    const int n     = blockIdx.x / CHUNKS;
    const int chunk = blockIdx.x % CHUNKS;
    const int sbase = chunk * SCHUNK;

    // Load W and bias into smem (coalesced)
    for (int i = t; i < K_ * C_; i += THREADS) Ws_f[i] = fc_w[i];
    if (t < K_) bsh[t] = fc_b[t];

    // vlad accumulator: thread (tk = t/16, ts = t%16) owns
    // rows k = 4*tk + i (i<4), cols c = ts + 16*j (j<8)
    const int tk = t >> 4;
    const int ts = t & 15;

    float vacc[4][8];
#pragma unroll
    for (int i = 0; i < 4; i++)
#pragma unroll
        for (int j = 0; j < 8; j++) vacc[i][j] = 0.0f;
    float asum_r = 0.0f;   // valid for t < K_

    const float* xn = x + (size_t)n * C_ * S_;

    for (int sub = 0; sub < NSUB; sub++) {
        const int s0 = sbase + sub * SP;

        __syncthreads();   // protect xs/lg reuse from previous sub-tile (and W load on iter 0)

        // ---- load x tile: xs[c][sp] ; coalesced along sp ----
#pragma unroll
        for (int r = 0; r < (C_ * SP) / THREADS; r++) {
            int idx = r * THREADS + t;
            int c = idx >> 6, sp = idx & 63;
            xs_f[c * (SP + 1) + sp] = xn[(size_t)c * S_ + s0 + sp];
        }
        __syncthreads();

        // ---- per-position L2 norm over channels ----
        {
            int sp = t & 63, p = t >> 6;
            float ss = 0.0f;
            const float* col = xs_f + sp;
#pragma unroll 8
            for (int c = p * 32; c < p * 32 + 32; c++) {
                float v = col[c * (SP + 1)];
                ss += v * v;
            }
            partb[p * SP + sp] = ss;
        }
        __syncthreads();
        if (t < SP) {
            float ss = partb[t] + partb[SP + t] + partb[2 * SP + t] + partb[3 * SP + t];
            inn[t] = 1.0f / fmaxf(sqrtf(ss), 1e-12f);
        }
        __syncthreads();

        // ---- normalize xs in place (so both GEMMs see normalized x) ----
#pragma unroll
        for (int r = 0; r < (C_ * SP) / THREADS; r++) {
            int idx = r * THREADS + t;
            int c = idx >> 6, sp = idx & 63;
            xs_f[c * (SP + 1) + sp] *= inn[sp];
        }
        __syncthreads();

        // ---- GEMM1: logits[k][sp] = sum_c W[k][c] * xs[c][sp] + b[k] ----
        // thread tile: k = 4*tk + i, sp = ts + 16*j  (conflict-free xs reads)
        {
            float acc[4][4];
#pragma unroll
            for (int i = 0; i < 4; i++)
#pragma unroll
                for (int j = 0; j < 4; j++) acc[i][j] = 0.0f;

#pragma unroll 4
            for (int c = 0; c < C_; c++) {
                float wv[4], xv[4];
#pragma unroll
                for (int i = 0; i < 4; i++) wv[i] = Ws_f[(4 * tk + i) * C_ + c];
#pragma unroll
                for (int j = 0; j < 4; j++) xv[j] = xs_f[c * (SP + 1) + ts + 16 * j];
#pragma unroll
                for (int i = 0; i < 4; i++)
#pragma unroll
                    for (int j = 0; j < 4; j++) acc[i][j] += wv[i] * xv[j];
            }
#pragma unroll
            for (int i = 0; i < 4; i++) {
                float b = bsh[4 * tk + i];
#pragma unroll
                for (int j = 0; j < 4; j++)
                    lg_f[(4 * tk + i) * (SP + 1) + ts + 16 * j] = acc[i][j] + b;
            }
        }
        __syncthreads();

        // ---- softmax over K per position (threads 0..63, one sp each) ----
        if (t < SP) {
            const int sp = t;
            float m = -1e30f;
#pragma unroll 8
            for (int k = 0; k < K_; k++) m = fmaxf(m, lg_f[k * (SP + 1) + sp]);
            float s = 0.0f;
#pragma unroll 8
            for (int k = 0; k < K_; k++) {
                float e = __expf(lg_f[k * (SP + 1) + sp] - m);
                lg_f[k * (SP + 1) + sp] = e;
                s += e;
            }
            float rs = 1.0f / s;
#pragma unroll 8
            for (int k = 0; k < K_; k++) lg_f[k * (SP + 1) + sp] *= rs;
        }
        __syncthreads();

        // ---- a_sum partials (read-only on lg; runs alongside GEMM2) ----
        if (t < K_) {
            float s = 0.0f;
#pragma unroll 8
            for (int sp = 0; sp < SP; sp++) s += lg_f[t * (SP + 1) + sp];
            asum_r += s;
        }

        // ---- GEMM2: vacc[k][c] += sum_sp soft[k][sp] * xs[c][sp] ----
        // thread tile: k = 4*tk + i, c = ts + 16*j (conflict-free xs reads)
#pragma unroll 2
        for (int sp = 0; sp < SP; sp++) {
            float sv[4], xv[8];
#pragma unroll
            for (int i = 0; i < 4; i++) sv[i] = lg_f[(4 * tk + i) * (SP + 1) + sp];
#pragma unroll
            for (int j = 0; j < 8; j++) xv[j] = xs_f[(ts + 16 * j) * (SP + 1) + sp];
#pragma unroll
            for (int i = 0; i < 4; i++)
#pragma unroll
                for (int j = 0; j < 8; j++) vacc[i][j] += sv[i] * xv[j];
        }
    }

    // ---- deterministic per-block partial writes ----
    float* vb = g_part + (size_t)blockIdx.x * (K_ * C_);
#pragma unroll
    for (int i = 0; i < 4; i++)
#pragma unroll
        for (int j = 0; j < 8; j++)
            vb[(4 * tk + i) * C_ + ts + 16 * j] = vacc[i][j];
    if (t < K_) g_apart[blockIdx.x * K_ + t] = asum_r;
}

__global__ __launch_bounds__(THREADS)
void netvlad_finalize_kernel(const float* __restrict__ centroids,
                             float* __restrict__ out)
{
    __shared__ float buf[K_ * C_];   // 32 KB
    __shared__ float as[K_];
    __shared__ float wssq[8];

    const int n = blockIdx.x;
    const int t = threadIdx.x;

    // reduce a_sum over chunks (fixed order => deterministic)
    if (t < K_) {
        float s = 0.0f;
#pragma unroll 8
        for (int ch = 0; ch < CHUNKS; ch++)
            s += g_apart[(n * CHUNKS + ch) * K_ + t];
        as[t] = s;
    }
    __syncthreads();

    // reduce vlad partials, subtract a_sum * centroid
    for (int i = t; i < K_ * C_; i += THREADS) {
        float s = 0.0f;
#pragma unroll 8
        for (int ch = 0; ch < CHUNKS; ch++)
            s += g_part[(size_t)(n * CHUNKS + ch) * (K_ * C_) + i];
        buf[i] = s - as[i >> 7] * centroids[i];
    }
    __syncthreads();

    // intra-normalization per k (one warp per row-set) + global ssq
    const int w = t >> 5, lane = t & 31;
    float gss = 0.0f;
    for (int k = w; k < K_; k += 8) {
        float v[4], ss = 0.0f;
#pragma unroll
        for (int j = 0; j < 4; j++) {
            v[j] = buf[k * C_ + lane * 4 + j];
            ss += v[j] * v[j];
        }
#pragma unroll
        for (int off = 16; off; off >>= 1) ss += __shfl_xor_sync(0xffffffffu, ss, off);
        float rn = 1.0f / fmaxf(sqrtf(ss), 1e-12f);
#pragma unroll
        for (int j = 0; j < 4; j++) {
            float o = v[j] * rn;
            buf[k * C_ + lane * 4 + j] = o;
            gss += o * o;
        }
    }
#pragma unroll
    for (int off = 16; off; off >>= 1) gss += __shfl_xor_sync(0xffffffffu, gss, off);
    if (lane == 0) wssq[w] = gss;
    __syncthreads();
    if (t == 0) {
        float s = 0.0f;
#pragma unroll
        for (int i = 0; i < 8; i++) s += wssq[i];
        wssq[0] = 1.0f / fmaxf(sqrtf(s), 1e-12f);
    }
    __syncthreads();

    const float rsc = wssq[0];
    for (int i = t; i < K_ * C_; i += THREADS)
        out[(size_t)n * K_ * C_ + i] = buf[i] * rsc;
}

extern "C" void kernel_launch(void* const* d_in, const int* in_sizes, int n_in,
                              void* d_out, int out_size)
{
    const float* x    = (const float*)d_in[0];   // [16,128,16384]
    const float* fc_w = (const float*)d_in[1];   // [64,128]
    const float* fc_b = (const float*)d_in[2];   // [64]
    const float* cent = (const float*)d_in[3];   // [64,128]
    float* out = (float*)d_out;                  // [16, 8192] fp32

    // 84.2 KB dynamic smem > 48 KB default -> opt in (host-side attr, not a stream op)
    cudaFuncSetAttribute(netvlad_main_kernel,
                         cudaFuncAttributeMaxDynamicSharedMemorySize,
                         (int)MAIN_SMEM_BYTES);

    netvlad_main_kernel<<<NBLOCKS, THREADS, MAIN_SMEM_BYTES>>>(x, fc_w, fc_b);
    netvlad_finalize_kernel<<<N_, THREADS>>>(cent, out);
}

// round 2
// speedup vs baseline: 1.2972x; 1.2972x over previous
#include <cuda_runtime.h>
#include <math.h>

typedef unsigned long long ull;

// Problem constants
#define N_      16
#define C_      128
#define S_      16384
#define K_      64

#define SP      64                  // positions per sub-tile
#define NSUBT   (S_ / SP)           // 256 sub-tiles per n
#define CHUNKS  37                  // blocks per n (592 total = 2 waves x 296 @ occ 2)
#define NBLOCKS (N_ * CHUNKS)       // 592
#define THREADS 256

// Deterministic scratch (allocations forbidden): per-block partials.
__device__ float g_part[(size_t)NBLOCKS * K_ * C_];   // 19.4 MB
__device__ float g_apart[NBLOCKS * K_];

// smem layout (floats)
#define XT_STRIDE 130               // [SP][130] : conflict-tuned row stride
#define SM_XT   0
#define SM_WS   (SM_XT + SP * XT_STRIDE)       // [K_][C_]
#define SM_LG   (SM_WS + K_ * C_)              // [K_][SP+1]
#define SM_BSH  (SM_LG + K_ * (SP + 1))        // [K_]
#define SM_FLTS (SM_BSH + K_)
#define MAIN_SMEM_BYTES (SM_FLTS * sizeof(float))

// ---- Blackwell packed fp32x2 helpers ----
__device__ __forceinline__ ull pk2(float x, float y) {
    ull r; asm("mov.b64 %0, {%1, %2};" : "=l"(r) : "f"(x), "f"(y)); return r;
}
__device__ __forceinline__ float2 upk2(ull v) {
    float2 r; asm("mov.b64 {%0, %1}, %2;" : "=f"(r.x), "=f"(r.y) : "l"(v)); return r;
}
__device__ __forceinline__ ull fma2(ull a, ull b, ull c) {
    ull d; asm("fma.rn.f32x2 %0, %1, %2, %3;" : "=l"(d) : "l"(a), "l"(b), "l"(c)); return d;
}

__global__ __launch_bounds__(THREADS, 2)
void netvlad_main_kernel(const float* __restrict__ x,
                         const float* __restrict__ fc_w,
                         const float* __restrict__ fc_b)
{
    extern __shared__ float sm[];
    float* xt  = sm + SM_XT;    // [SP][130]  x tile, transposed (sp-major)
    float* Ws  = sm + SM_WS;    // [K_][C_]
    float* lg  = sm + SM_LG;    // [K_][SP+1] logits -> softmax (scaled in place)
    float* bsh = sm + SM_BSH;   // [K_]

    const int t  = threadIdx.x;
    const int n  = blockIdx.x / CHUNKS;
    const int ci = blockIdx.x % CHUNKS;
    const int sub_lo = (ci * NSUBT) / CHUNKS;
    const int sub_hi = ((ci + 1) * NSUBT) / CHUNKS;

    for (int i = t; i < K_ * C_; i += THREADS) Ws[i] = fc_w[i];
    if (t < K_) bsh[t] = fc_b[t];

    const int tk  = t >> 4;    // 0..15 : k-group
    const int ts  = t & 15;    // 0..15 : sp/c-group
    const int spq = t >> 2;    // 0..63 : quad-mapped position
    const int pq  = t & 3;     // 0..3  : quad member

    // persistent packed vlad accumulator: k = 4*tk+i, c-pair cp = ts+16*j
    ull vacc[4][4];
#pragma unroll
    for (int i = 0; i < 4; i++)
#pragma unroll
        for (int j = 0; j < 4; j++) vacc[i][j] = 0ULL;
    float asum_r = 0.0f;       // meaningful only on pq==0 (k = spq)

    const float* xn = x + (size_t)n * C_ * S_;

    for (int sub = sub_lo; sub < sub_hi; sub++) {
        const int s0 = sub * SP;

        __syncthreads();   // guard: prev iter's xt/lg readers done

        // ---- load x tile, transposed into xt[sp][c] ----
#pragma unroll
        for (int r = 0; r < (C_ * SP) / THREADS; r++) {
            int idx = r * THREADS + t;
            int c = idx >> 6, sp = idx & 63;
            xt[sp * XT_STRIDE + c] = xn[(size_t)c * S_ + s0 + sp];
        }
        __syncthreads();

        // ---- per-position L2 normalize (quad of lanes per sp, shuffle reduce) ----
        {
            float2* q = (float2*)(xt + spq * XT_STRIDE + pq * 32);
            ull ssp = 0ULL;
#pragma unroll
            for (int i = 0; i < 16; i++) {
                float2 v = q[i];
                ull up = pk2(v.x, v.y);
                ssp = fma2(up, up, ssp);
            }
            float2 s2 = upk2(ssp);
            float ss = s2.x + s2.y;
            ss += __shfl_xor_sync(0xffffffffu, ss, 1);
            ss += __shfl_xor_sync(0xffffffffu, ss, 2);
            float rin = 1.0f / fmaxf(sqrtf(ss), 1e-12f);
#pragma unroll
            for (int i = 0; i < 16; i++) {
                float2 v = q[i];
                v.x *= rin; v.y *= rin;
                q[i] = v;
            }
        }
        __syncthreads();

        // ---- GEMM1: lg[k][sp] = sum_c W[k][c]*xt[sp][c] + b[k]  (packed over c) ----
        {
            ull acc[4][4];
#pragma unroll
            for (int i = 0; i < 4; i++)
#pragma unroll
                for (int j = 0; j < 4; j++) acc[i][j] = 0ULL;

#pragma unroll 2
            for (int cp = 0; cp < C_ / 2; cp++) {
                ull wp[4], xp[4];
#pragma unroll
                for (int i = 0; i < 4; i++) {
                    float2 v = *(const float2*)(Ws + (4 * tk + i) * C_ + 2 * cp);
                    wp[i] = pk2(v.x, v.y);
                }
#pragma unroll
                for (int j = 0; j < 4; j++) {
                    float2 v = *(const float2*)(xt + (ts + 16 * j) * XT_STRIDE + 2 * cp);
                    xp[j] = pk2(v.x, v.y);
                }
#pragma unroll
                for (int i = 0; i < 4; i++)
#pragma unroll
                    for (int j = 0; j < 4; j++)
                        acc[i][j] = fma2(wp[i], xp[j], acc[i][j]);
            }
#pragma unroll
            for (int i = 0; i < 4; i++) {
                float bb = bsh[4 * tk + i];
#pragma unroll
                for (int j = 0; j < 4; j++) {
                    float2 a = upk2(acc[i][j]);
                    lg[(4 * tk + i) * (SP + 1) + ts + 16 * j] = a.x + a.y + bb;
                }
            }
        }
        __syncthreads();

        // ---- softmax over K per position (quad of lanes per sp, shuffle reduce) ----
        {
            float m = -1e30f;
#pragma unroll
            for (int kk = 0; kk < 16; kk++)
                m = fmaxf(m, lg[(16 * pq + kk) * (SP + 1) + spq]);
            m = fmaxf(m, __shfl_xor_sync(0xffffffffu, m, 1));
            m = fmaxf(m, __shfl_xor_sync(0xffffffffu, m, 2));
            float s = 0.0f;
#pragma unroll
            for (int kk = 0; kk < 16; kk++) {
                float e = __expf(lg[(16 * pq + kk) * (SP + 1) + spq] - m);
                lg[(16 * pq + kk) * (SP + 1) + spq] = e;
                s += e;
            }
            s += __shfl_xor_sync(0xffffffffu, s, 1);
            s += __shfl_xor_sync(0xffffffffu, s, 2);
            float rs = 1.0f / s;
#pragma unroll
            for (int kk = 0; kk < 16; kk++)
                lg[(16 * pq + kk) * (SP + 1) + spq] *= rs;
        }
        __syncthreads();

        // ---- a_sum partials: k = spq, quad splits sp range, shuffle reduce ----
        {
            float s = 0.0f;
#pragma unroll
            for (int i = 0; i < 16; i++)
                s += lg[spq * (SP + 1) + 16 * pq + i];
            s += __shfl_xor_sync(0xffffffffu, s, 1);
            s += __shfl_xor_sync(0xffffffffu, s, 2);
            if (pq == 0) asum_r += s;
        }

        // ---- GEMM2: vacc[k][2cp..2cp+1] += soft[k][sp] * xt[sp][2cp..]  (packed over c) ----
#pragma unroll 1
        for (int sp = 0; sp < SP; sp++) {
            ull svp[4], xp[4];
#pragma unroll
            for (int i = 0; i < 4; i++) {
                float sv = lg[(4 * tk + i) * (SP + 1) + sp];
                svp[i] = pk2(sv, sv);
            }
#pragma unroll
            for (int j = 0; j < 4; j++) {
                float2 v = *(const float2*)(xt + sp * XT_STRIDE + 2 * (ts + 16 * j));
                xp[j] = pk2(v.x, v.y);
            }
#pragma unroll
            for (int i = 0; i < 4; i++)
#pragma unroll
                for (int j = 0; j < 4; j++)
                    vacc[i][j] = fma2(svp[i], xp[j], vacc[i][j]);
        }
    }

    // ---- deterministic per-block partial writes (64-bit stores) ----
    float* vb = g_part + (size_t)blockIdx.x * (K_ * C_);
#pragma unroll
    for (int i = 0; i < 4; i++)
#pragma unroll
        for (int j = 0; j < 4; j++) {
            float2 a = upk2(vacc[i][j]);
            *(float2*)(vb + (4 * tk + i) * C_ + 2 * (ts + 16 * j)) = a;
        }
    if (pq == 0) g_apart[blockIdx.x * K_ + spq] = asum_r;
}

// F1: one block per (k, n): reduce 37 chunk partials, subtract a_sum*centroid,
// intra-normalize the row, write normalized row into chunk-0 slot + ssq scalar.
__global__ __launch_bounds__(128)
void netvlad_reduce_kernel(const float* __restrict__ centroids)
{
    __shared__ float asv[CHUNKS];
    __shared__ float wred[4];

    const int k = blockIdx.x;
    const int n = blockIdx.y;
    const int c = threadIdx.x;

    if (c < CHUNKS) asv[c] = g_apart[(n * CHUNKS + c) * K_ + k];
    __syncthreads();
    float a = 0.0f;
#pragma unroll
    for (int ch = 0; ch < CHUNKS; ch++) a += asv[ch];

    float s = 0.0f;
#pragma unroll 4
    for (int ch = 0; ch < CHUNKS; ch++)
        s += g_part[(size_t)(n * CHUNKS + ch) * (K_ * C_) + k * C_ + c];

    float val = s - a * centroids[k * C_ + c];

    float ss = val * val;
#pragma unroll
    for (int off = 16; off; off >>= 1) ss += __shfl_xor_sync(0xffffffffu, ss, off);
    if ((c & 31) == 0) wred[c >> 5] = ss;
    __syncthreads();
    float tot = wred[0] + wred[1] + wred[2] + wred[3];
    float rn = 1.0f / fmaxf(sqrtf(tot), 1e-12f);

    g_part[(size_t)(n * CHUNKS) * (K_ * C_) + k * C_ + c] = val * rn;
    if (c == 0) g_apart[(n * CHUNKS) * K_ + k] = tot * rn * rn;  // ||row||^2 after norm
}

// F2: per n, global L2 normalize the 8192-dim vector.
__global__ __launch_bounds__(256)
void netvlad_final_kernel(float* __restrict__ out)
{
    __shared__ float kss[K_];
    __shared__ float rs_sh;

    const int n = blockIdx.x;
    const int t = threadIdx.x;

    if (t < K_) kss[t] = g_apart[(n * CHUNKS) * K_ + t];
    __syncthreads();
    if (t == 0) {
        float tot = 0.0f;
#pragma unroll
        for (int k = 0; k < K_; k++) tot += kss[k];
        rs_sh = 1.0f / fmaxf(sqrtf(tot), 1e-12f);
    }
    __syncthreads();
    const float rsc = rs_sh;

    const float* src = g_part + (size_t)(n * CHUNKS) * (K_ * C_);
#pragma unroll 4
    for (int i = t; i < K_ * C_; i += 256)
        out[(size_t)n * K_ * C_ + i] = src[i] * rsc;
}

extern "C" void kernel_launch(void* const* d_in, const int* in_sizes, int n_in,
                              void* d_out, int out_size)
{
    const float* x    = (const float*)d_in[0];   // [16,128,16384]
    const float* fc_w = (const float*)d_in[1];   // [64,128]
    const float* fc_b = (const float*)d_in[2];   // [64]
    const float* cent = (const float*)d_in[3];   // [64,128]
    float* out = (float*)d_out;                  // [16, 8192] fp32

    cudaFuncSetAttribute(netvlad_main_kernel,
                         cudaFuncAttributeMaxDynamicSharedMemorySize,
                         (int)MAIN_SMEM_BYTES);

    netvlad_main_kernel<<<NBLOCKS, THREADS, MAIN_SMEM_BYTES>>>(x, fc_w, fc_b);
    netvlad_reduce_kernel<<<dim3(K_, N_), 128>>>(cent);
    netvlad_final_kernel<<<N_, 256>>>(out);
}